// round 3
// baseline (speedup 1.0000x reference)
#include <cuda_runtime.h>
#include <math.h>

#define H 128
#define NGR 256
#define NCLS 10
#define NMAX 50048
#define EMAX 600064
#define NB_STATS 256
#define SCAN_BLK 512
#define MAX_SB ((NMAX + SCAN_BLK - 1) / SCAN_BLK)

// ---------------- device scratch (static; no allocation allowed) ----------------
__device__ float g_bufA[(size_t)NMAX * H];   // ping: GEMM output p
__device__ float g_bufB[(size_t)NMAX * H];   // pong: layer activations h
__device__ float g_dinv[NMAX];
__device__ int   g_deg[NMAX];
__device__ int   g_rowptr[NMAX + 1];
__device__ int   g_cursor[NMAX];
__device__ int   g_srcs[EMAX];
__device__ int   g_bsum[MAX_SB + 1];
__device__ float g_psum[NB_STATS * H];
__device__ float g_psq[NB_STATS * H];
__device__ float g_Wf[H * H];                // BN-folded weight (rows scaled by s)
__device__ float g_cvec[H];                  // pre-aggregation bias  c = t @ W
__device__ float g_bf[H];                    // post-aggregation bias (conv bias / folded fc bias)
__device__ float g_pool[NGR * H];
__device__ int   g_flags[2];                 // [0]=edge idx is int64, [1]=batch is int64

// ---------------- dtype-flexible index load ----------------
__device__ __forceinline__ int edge_idx(const void* p, long long i) {
    return g_flags[0] ? (int)((const long long*)p)[i] : ((const int*)p)[i];
}

__global__ void k_detect(const void* ei, const void* bt, int E, int N) {
    if (threadIdx.x == 0 && blockIdx.x == 0) {
        // If the data is really int32, reading as u64 packs two values; the high
        // half is a random node index (nonzero w.h.p.) -> value >= 2^31.
        const unsigned long long* e64 = (const unsigned long long*)ei;
        int f = 1;
        for (int j = 0; j < 32; j++)
            if (e64[j] >= (1ULL << 31)) { f = 0; break; }
        g_flags[0] = f;
        const unsigned long long* b64 = (const unsigned long long*)bt;
        int f2 = 1;
        int half = N / 2;   // batch sorted: sample mid values (~128, nonzero)
        for (int j = half - 32; j < half; j++)
            if (b64[j] >= (1ULL << 31)) { f2 = 0; break; }
        g_flags[1] = f2;
    }
}

__global__ void k_zero(int N) {
    int tot = (N > NGR * H) ? N : (NGR * H);
    for (int i = blockIdx.x * blockDim.x + threadIdx.x; i < tot; i += gridDim.x * blockDim.x) {
        if (i < N) g_deg[i] = 0;
        if (i < NGR * H) g_pool[i] = 0.f;
    }
}

__global__ void k_hist(const void* ei, int E) {
    int e = blockIdx.x * blockDim.x + threadIdx.x;
    if (e < E) {
        int d = edge_idx(ei, (long long)E + e);
        atomicAdd(&g_deg[d], 1);
    }
}

__global__ void k_dinv(int N) {
    int i = blockIdx.x * blockDim.x + threadIdx.x;
    if (i < N) g_dinv[i] = rsqrtf((float)g_deg[i] + 1.0f);
}

// ---------------- CSR build: scan of in-degrees ----------------
__global__ void k_scan1(int N) {
    __shared__ int sh[SCAN_BLK];
    int t = threadIdx.x;
    int i = blockIdx.x * SCAN_BLK + t;
    int v = (i < N) ? g_deg[i] : 0;
    sh[t] = v;
    __syncthreads();
    for (int off = 1; off < SCAN_BLK; off <<= 1) {
        int add = (t >= off) ? sh[t - off] : 0;
        __syncthreads();
        sh[t] += add;
        __syncthreads();
    }
    if (i < N) g_rowptr[i] = sh[t] - v;        // local exclusive
    if (t == SCAN_BLK - 1) g_bsum[blockIdx.x] = sh[t];
}

__global__ void k_scan2(int nb) {
    if (threadIdx.x == 0 && blockIdx.x == 0) {
        int acc = 0;
        for (int b = 0; b < nb; b++) { int v = g_bsum[b]; g_bsum[b] = acc; acc += v; }
    }
}

__global__ void k_scan3(int N, int E) {
    int i = blockIdx.x * blockDim.x + threadIdx.x;
    if (i < N) {
        int r = g_rowptr[i] + g_bsum[i / SCAN_BLK];
        g_rowptr[i] = r;
        g_cursor[i] = r;
    }
    if (i == 0) g_rowptr[N] = E;
}

__global__ void k_fill(const void* ei, int E) {
    int e = blockIdx.x * blockDim.x + threadIdx.x;
    if (e < E) {
        int s = edge_idx(ei, e);
        int d = edge_idx(ei, (long long)E + e);
        int pos = atomicAdd(&g_cursor[d], 1);
        g_srcs[pos] = s;
    }
}

// ---------------- BN statistics (two-stage column reduction) ----------------
__global__ void k_stats(const float* __restrict__ h, int N) {
    int j = threadIdx.x;     // column
    int b = blockIdx.x;
    float s = 0.f, q = 0.f;
    for (int r = b; r < N; r += NB_STATS) {
        float v = h[(size_t)r * H + j];
        s += v; q += v * v;
    }
    g_psum[b * H + j] = s;
    g_psq[b * H + j]  = q;
}

// Fold BN (per-column affine y = x*s + t) into the FOLLOWING conv weight.
// BN precedes the graph aggregation, so the shift term t@W must be added
// BEFORE aggregation (g_cvec), while the conv bias is added AFTER (g_bf).
__global__ void k_fold(const float* __restrict__ W, const float* __restrict__ bias_in,
                       const float* __restrict__ gamma, const float* __restrict__ beta,
                       int Nrows) {
    int j = threadIdx.x;
    float s = 0.f, q = 0.f;
    for (int b = 0; b < NB_STATS; b++) { s += g_psum[b * H + j]; q += g_psq[b * H + j]; }
    float mean = s / (float)Nrows;
    float var  = q / (float)Nrows - mean * mean;
    float sj = rsqrtf(var + 1e-5f) * gamma[j];
    float tj = beta[j] - mean * sj;
    __shared__ float tsh[H];
    tsh[j] = tj;
    for (int k = 0; k < H; k++) g_Wf[j * H + k] = sj * W[j * H + k];
    __syncthreads();
    float cc = 0.f;
    for (int jj = 0; jj < H; jj++) cc += tsh[jj] * W[jj * H + j];
    g_cvec[j] = cc;            // pre-aggregation constant (t @ W)
    g_bf[j] = bias_in[j];      // post-aggregation conv bias
}

// ---------------- fp32 GEMM: out = A[nrows,128] @ B[128,128], fused epilogue ----------------
// mode 0: out = (acc + cvec[col]) * dinv[row]    (GCN pre-aggregation, B = g_Wf)
// mode 1: out = relu(acc + bias[col])            (gate hidden layer, B = arg)
__global__ void __launch_bounds__(256) k_mm(const float* __restrict__ A,
                                            const float* __restrict__ Bopt,
                                            const float* __restrict__ bias,
                                            float* __restrict__ out,
                                            int nrows, int mode) {
    const float* B = Bopt ? Bopt : g_Wf;
    __shared__ float As[32][132];
    __shared__ float Bs[32][132];
    int tid = threadIdx.x;
    int tr = tid >> 4, tc = tid & 15;
    int row0 = blockIdx.x * 128;
    float acc[8][8];
#pragma unroll
    for (int i = 0; i < 8; i++)
#pragma unroll
        for (int j = 0; j < 8; j++) acc[i][j] = 0.f;

    for (int k0 = 0; k0 < H; k0 += 32) {
#pragma unroll
        for (int i = 0; i < 4; i++) {
            int r = (tid >> 3) + i * 32;
            int c = (tid & 7) * 4;
            int gr = row0 + r;
            float4 v = make_float4(0.f, 0.f, 0.f, 0.f);
            if (gr < nrows) v = *(const float4*)&A[(size_t)gr * H + k0 + c];
            As[c + 0][r] = v.x; As[c + 1][r] = v.y; As[c + 2][r] = v.z; As[c + 3][r] = v.w;
        }
#pragma unroll
        for (int i = 0; i < 4; i++) {
            int r = (tid >> 5) + i * 8;
            int c = (tid & 31) * 4;
            *(float4*)&Bs[r][c] = *(const float4*)&B[(size_t)(k0 + r) * H + c];
        }
        __syncthreads();
#pragma unroll
        for (int kk = 0; kk < 32; kk++) {
            float a[8], bv[8];
#pragma unroll
            for (int i = 0; i < 8; i++) a[i] = As[kk][tr * 8 + i];
#pragma unroll
            for (int j = 0; j < 8; j++) bv[j] = Bs[kk][tc * 8 + j];
#pragma unroll
            for (int i = 0; i < 8; i++)
#pragma unroll
                for (int j = 0; j < 8; j++)
                    acc[i][j] = fmaf(a[i], bv[j], acc[i][j]);
        }
        __syncthreads();
    }
#pragma unroll
    for (int i = 0; i < 8; i++) {
        int gr = row0 + tr * 8 + i;
        if (gr >= nrows) continue;
        if (mode == 0) {
            float d = g_dinv[gr];
#pragma unroll
            for (int j = 0; j < 8; j++) {
                int cc = tc * 8 + j;
                out[(size_t)gr * H + cc] = (acc[i][j] + g_cvec[cc]) * d;
            }
        } else {
#pragma unroll
            for (int j = 0; j < 8; j++) {
                int cc = tc * 8 + j;
                out[(size_t)gr * H + cc] = fmaxf(acc[i][j] + bias[cc], 0.f);
            }
        }
    }
}

// ---------------- CSR gather aggregation + relu epilogue ----------------
// out[i] = relu( dinv[i] * (p[i] + sum_{e: dst=i} p[src_e]) + conv_bias )
__global__ void k_gather(const float* __restrict__ p, float* __restrict__ out, int N) {
    int w = (blockIdx.x * blockDim.x + threadIdx.x) >> 5;
    int lane = threadIdx.x & 31;
    if (w >= N) return;
    float4 acc = *(const float4*)&p[(size_t)w * H + lane * 4];
    int beg = g_rowptr[w], end = g_rowptr[w + 1];
    for (int e = beg; e < end; e++) {
        int s = g_srcs[e];
        float4 v = *(const float4*)&p[(size_t)s * H + lane * 4];
        acc.x += v.x; acc.y += v.y; acc.z += v.z; acc.w += v.w;
    }
    float d = g_dinv[w];
    float4 bb = *(const float4*)&g_bf[lane * 4];
    float4 o;
    o.x = fmaxf(fmaf(acc.x, d, bb.x), 0.f);
    o.y = fmaxf(fmaf(acc.y, d, bb.y), 0.f);
    o.z = fmaxf(fmaf(acc.z, d, bb.z), 0.f);
    o.w = fmaxf(fmaf(acc.w, d, bb.w), 0.f);
    *(float4*)&out[(size_t)w * H + lane * 4] = o;
}

// ---------------- gate scalar + weighted pooling ----------------
__global__ void k_gatepool(const float* __restrict__ r, const float* __restrict__ h,
                           const float* __restrict__ w2, const float* __restrict__ b2,
                           const void* batch, int N) {
    int w = (blockIdx.x * blockDim.x + threadIdx.x) >> 5;
    int lane = threadIdx.x & 31;
    if (w >= N) return;
    float4 rv = *(const float4*)&r[(size_t)w * H + lane * 4];
    float4 wv = *(const float4*)&w2[lane * 4];
    float d = rv.x * wv.x + rv.y * wv.y + rv.z * wv.z + rv.w * wv.w;
#pragma unroll
    for (int o = 16; o; o >>= 1) d += __shfl_xor_sync(0xffffffffu, d, o);
    float gate = 1.f / (1.f + expf(-(d + b2[0])));
    int b = g_flags[1] ? (int)((const long long*)batch)[w] : ((const int*)batch)[w];
    float4 hv = *(const float4*)&h[(size_t)w * H + lane * 4];
    float* dst = &g_pool[b * H + lane * 4];
    atomicAdd(dst + 0, hv.x * gate);
    atomicAdd(dst + 1, hv.y * gate);
    atomicAdd(dst + 2, hv.z * gate);
    atomicAdd(dst + 3, hv.w * gate);
}

// ---------------- BN over pooled graphs, folded into fc (no aggregation follows) ----------------
__global__ void k_foldfc(const float* __restrict__ fcW, const float* __restrict__ fcb,
                         const float* __restrict__ gg, const float* __restrict__ gb) {
    int j = threadIdx.x;
    float s = 0.f, q = 0.f;
    for (int r = 0; r < NGR; r++) {
        float v = g_pool[r * H + j];
        s += v; q += v * v;
    }
    float mean = s / (float)NGR;
    float var = q / (float)NGR - mean * mean;
    float sj = rsqrtf(var + 1e-5f) * gg[j];
    float tj = gb[j] - mean * sj;
    __shared__ float tsh[H];
    tsh[j] = tj;
    for (int k = 0; k < H; k++) g_Wf[j * H + k] = sj * fcW[j * H + k];
    __syncthreads();
    float bb = fcb[j];
    for (int jj = 0; jj < H; jj++) bb += tsh[jj] * fcW[jj * H + j];
    g_bf[j] = bb;
}

// ---------------- fc + classifier + log_softmax ----------------
__global__ void k_final(const float* __restrict__ clsW, const float* __restrict__ clsb,
                        float* __restrict__ out) {
    __shared__ float gs[H], ys[H], ls[NCLS];
    int g = blockIdx.x, t = threadIdx.x;
    gs[t] = g_pool[g * H + t];
    __syncthreads();
    float a = g_bf[t];
#pragma unroll 8
    for (int j = 0; j < H; j++) a += gs[j] * g_Wf[j * H + t];
    ys[t] = fmaxf(a, 0.f);
    __syncthreads();
    if (t < NCLS) {
        float l = clsb[t];
        for (int k = 0; k < H; k++) l += ys[k] * clsW[k * NCLS + t];
        ls[t] = l;
    }
    __syncthreads();
    if (t == 0) {
        float m = ls[0];
        for (int c = 1; c < NCLS; c++) m = fmaxf(m, ls[c]);
        float se = 0.f;
        for (int c = 0; c < NCLS; c++) se += expf(ls[c] - m);
        float lse = m + logf(se);
        for (int c = 0; c < NCLS; c++) out[g * NCLS + c] = ls[c] - lse;
    }
}

// ---------------- host orchestration (graph-capturable: launches only) ----------------
extern "C" void kernel_launch(void* const* d_in, const int* in_sizes, int n_in,
                              void* d_out, int out_size) {
    const float* x           = (const float*)d_in[0];
    const void*  ei          = d_in[1];
    const void*  batch       = d_in[2];
    const float* bn_feat_g   = (const float*)d_in[3];
    const float* bn_feat_b   = (const float*)d_in[4];
    const float* conv_feat_W = (const float*)d_in[5];
    const float* conv_feat_b = (const float*)d_in[6];
    const float* conv_W      = (const float*)d_in[7];
    const float* conv_b      = (const float*)d_in[8];
    const float* bn_conv_g   = (const float*)d_in[9];
    const float* bn_conv_b   = (const float*)d_in[10];
    const float* gate_W1     = (const float*)d_in[11];
    const float* gate_b1     = (const float*)d_in[12];
    const float* gate_W2     = (const float*)d_in[13];
    const float* gate_b2     = (const float*)d_in[14];
    const float* fc_W        = (const float*)d_in[15];
    const float* fc_b        = (const float*)d_in[16];
    const float* bn_fc_g     = (const float*)d_in[17];
    const float* bn_fc_b     = (const float*)d_in[18];
    const float* cls_W       = (const float*)d_in[19];
    const float* cls_b       = (const float*)d_in[20];

    int N = in_sizes[0] / H;
    int E = in_sizes[1] / 2;

    float *bufA = nullptr, *bufB = nullptr;
    cudaGetSymbolAddress((void**)&bufA, g_bufA);
    cudaGetSymbolAddress((void**)&bufB, g_bufB);

    int nb = (N + SCAN_BLK - 1) / SCAN_BLK;
    int mmg = (N + 127) / 128;

    k_detect<<<1, 32>>>(ei, batch, E, N);
    k_zero<<<256, 256>>>(N);
    k_hist<<<(E + 255) / 256, 256>>>(ei, E);
    k_dinv<<<(N + 255) / 256, 256>>>(N);
    k_scan1<<<nb, SCAN_BLK>>>(N);
    k_scan2<<<1, 32>>>(nb);
    k_scan3<<<(N + 255) / 256, 256>>>(N, E);
    k_fill<<<(E + 255) / 256, 256>>>(ei, E);

    // layer 0: BN(x) folded into conv_feat
    k_stats<<<NB_STATS, H>>>(x, N);
    k_fold<<<1, H>>>(conv_feat_W, conv_feat_b, bn_feat_g, bn_feat_b, N);
    k_mm<<<mmg, 256>>>(x, nullptr, nullptr, bufA, N, 0);
    k_gather<<<(N + 7) / 8, 256>>>(bufA, bufB, N);

    // layers 1..3
    for (int l = 0; l < 3; l++) {
        k_stats<<<NB_STATS, H>>>(bufB, N);
        k_fold<<<1, H>>>(conv_W + (size_t)l * H * H, conv_b + l * H,
                         bn_conv_g + l * H, bn_conv_b + l * H, N);
        k_mm<<<mmg, 256>>>(bufB, nullptr, nullptr, bufA, N, 0);
        k_gather<<<(N + 7) / 8, 256>>>(bufA, bufB, N);
    }

    // gate MLP + pooling
    k_mm<<<mmg, 256>>>(bufB, gate_W1, gate_b1, bufA, N, 1);
    k_gatepool<<<((size_t)N * 32 + 255) / 256, 256>>>(bufA, bufB, gate_W2, gate_b2, batch, N);

    // fc + classifier + log_softmax
    k_foldfc<<<1, H>>>(fc_W, fc_b, bn_fc_g, bn_fc_b);
    k_final<<<NGR, H>>>(cls_W, cls_b, (float*)d_out);
}

// round 5
// speedup vs baseline: 1.0983x; 1.0983x over previous
#include <cuda_runtime.h>
#include <math.h>
#include <stdint.h>

#define H 128
#define NGR 256
#define NCLS 10
#define NMAX 50048
#define EMAX 600064
#define NB_STATS 256
#define SCAN_BLK 512
#define MAX_SB ((NMAX + SCAN_BLK - 1) / SCAN_BLK)

#define AS_STRIDE 132   // bank-conflict-free for A fragment pattern (4g+t)
#define BS_STRIDE 136   // bank-conflict-free for B fragment pattern (8t+g)
#define SMEM_MM ((128 * AS_STRIDE + 128 * BS_STRIDE) * 4)

// ---------------- device scratch (static; no allocation allowed) ----------------
__device__ float g_bufA[(size_t)NMAX * H];   // ping: GEMM output p
__device__ float g_bufB[(size_t)NMAX * H];   // pong: layer activations h
__device__ float g_dinv[NMAX];
__device__ int   g_deg[NMAX];
__device__ int   g_rowptr[NMAX + 1];
__device__ int   g_cursor[NMAX];
__device__ int   g_srcs[EMAX];
__device__ int   g_bsum[MAX_SB + 1];
__device__ float g_psum[NB_STATS * H];
__device__ float g_psq[NB_STATS * H];
__device__ float g_Wf[H * H];                // folded fc weight (k_foldfc/k_final)
__device__ float g_Bf[H * H];                // BN-folded conv weight [K,N] for mma GEMM
__device__ float g_cvec[H];                  // pre-aggregation bias  c = t @ W
__device__ float g_bf[H];                    // post-aggregation bias
__device__ float g_pool[NGR * H];
__device__ int   g_flags[2];                 // [0]=edge idx is int64, [1]=batch is int64

// ---------------- helpers ----------------
__device__ __forceinline__ float to_tf32(float x) {
    float y;
    asm("cvt.rna.tf32.f32 %0, %1;" : "=f"(y) : "f"(x));
    return y;
}
__device__ __forceinline__ void mma8(float* acc, uint32_t a0, uint32_t a1, uint32_t a2,
                                     uint32_t a3, uint32_t b0, uint32_t b1) {
    asm volatile(
        "mma.sync.aligned.m16n8k8.row.col.f32.tf32.tf32.f32 "
        "{%0,%1,%2,%3},{%4,%5,%6,%7},{%8,%9},{%0,%1,%2,%3};"
        : "+f"(acc[0]), "+f"(acc[1]), "+f"(acc[2]), "+f"(acc[3])
        : "r"(a0), "r"(a1), "r"(a2), "r"(a3), "r"(b0), "r"(b1));
}

// ---------------- dtype-flexible index load ----------------
__device__ __forceinline__ int edge_idx(const void* p, long long i) {
    return g_flags[0] ? (int)((const long long*)p)[i] : ((const int*)p)[i];
}

__global__ void k_detect(const void* ei, const void* bt, int E, int N) {
    if (threadIdx.x == 0 && blockIdx.x == 0) {
        const unsigned long long* e64 = (const unsigned long long*)ei;
        int f = 1;
        for (int j = 0; j < 32; j++)
            if (e64[j] >= (1ULL << 31)) { f = 0; break; }
        g_flags[0] = f;
        const unsigned long long* b64 = (const unsigned long long*)bt;
        int f2 = 1;
        int half = N / 2;
        for (int j = half - 32; j < half; j++)
            if (b64[j] >= (1ULL << 31)) { f2 = 0; break; }
        g_flags[1] = f2;
    }
}

__global__ void k_zero(int N) {
    int tot = (N > NGR * H) ? N : (NGR * H);
    for (int i = blockIdx.x * blockDim.x + threadIdx.x; i < tot; i += gridDim.x * blockDim.x) {
        if (i < N) g_deg[i] = 0;
        if (i < NGR * H) g_pool[i] = 0.f;
    }
}

__global__ void k_hist(const void* ei, int E) {
    int e = blockIdx.x * blockDim.x + threadIdx.x;
    if (e < E) atomicAdd(&g_deg[edge_idx(ei, (long long)E + e)], 1);
}

__global__ void k_dinv(int N) {
    int i = blockIdx.x * blockDim.x + threadIdx.x;
    if (i < N) g_dinv[i] = rsqrtf((float)g_deg[i] + 1.0f);
}

// ---------------- CSR build ----------------
__global__ void k_scan1(int N) {
    __shared__ int sh[SCAN_BLK];
    int t = threadIdx.x;
    int i = blockIdx.x * SCAN_BLK + t;
    int v = (i < N) ? g_deg[i] : 0;
    sh[t] = v;
    __syncthreads();
    for (int off = 1; off < SCAN_BLK; off <<= 1) {
        int add = (t >= off) ? sh[t - off] : 0;
        __syncthreads();
        sh[t] += add;
        __syncthreads();
    }
    if (i < N) g_rowptr[i] = sh[t] - v;
    if (t == SCAN_BLK - 1) g_bsum[blockIdx.x] = sh[t];
}

__global__ void k_scan2(int nb) {
    if (threadIdx.x == 0 && blockIdx.x == 0) {
        int acc = 0;
        for (int b = 0; b < nb; b++) { int v = g_bsum[b]; g_bsum[b] = acc; acc += v; }
    }
}

__global__ void k_scan3(int N, int E) {
    int i = blockIdx.x * blockDim.x + threadIdx.x;
    if (i < N) {
        int r = g_rowptr[i] + g_bsum[i / SCAN_BLK];
        g_rowptr[i] = r;
        g_cursor[i] = r;
    }
    if (i == 0) g_rowptr[N] = E;
}

__global__ void k_fill(const void* ei, int E) {
    int e = blockIdx.x * blockDim.x + threadIdx.x;
    if (e < E) {
        int s = edge_idx(ei, e);
        int d = edge_idx(ei, (long long)E + e);
        g_srcs[atomicAdd(&g_cursor[d], 1)] = s;
    }
}

// ---------------- BN statistics ----------------
__global__ void k_stats(const float* __restrict__ h, int N) {
    int j = threadIdx.x;
    int b = blockIdx.x;
    float s = 0.f, q = 0.f;
    for (int r = b; r < N; r += NB_STATS) {
        float v = h[(size_t)r * H + j];
        s += v; q += v * v;
    }
    g_psum[b * H + j] = s;
    g_psq[b * H + j]  = q;
}

// Fold BN (y = x*s + t) into the following conv: Bf[k][n] = s_k * W[k][n];
// shift term c = t @ W rides pre-aggregation; conv bias post-aggregation.
__global__ void k_fold(const float* __restrict__ W, const float* __restrict__ bias_in,
                       const float* __restrict__ gamma, const float* __restrict__ beta,
                       int Nrows) {
    int j = threadIdx.x;
    float s = 0.f, q = 0.f;
    for (int b = 0; b < NB_STATS; b++) { s += g_psum[b * H + j]; q += g_psq[b * H + j]; }
    float mean = s / (float)Nrows;
    float var  = q / (float)Nrows - mean * mean;
    float sj = rsqrtf(var + 1e-5f) * gamma[j];
    float tj = beta[j] - mean * sj;
    __shared__ float tsh[H];
    tsh[j] = tj;
    for (int k = 0; k < H; k++) g_Bf[j * H + k] = sj * W[j * H + k];  // row j scaled
    __syncthreads();
    float cc = 0.f;
    for (int jj = 0; jj < H; jj++) cc += tsh[jj] * W[jj * H + j];
    g_cvec[j] = cc;
    g_bf[j] = bias_in[j];
}

__global__ void k_prepgate(const float* __restrict__ W) {
    int j = threadIdx.x;
    for (int k = 0; k < H; k++) g_Bf[j * H + k] = W[j * H + k];
}

// ---------------- tensor-core GEMM via mma.sync tf32, 3xTF32 split ----------------
// out[128tile, 128] = A @ g_Bf, fused epilogue.
// mode 0: out = (acc + cvec[col]) * dinv[row]
// mode 1: out = relu(acc + bias[col])
__global__ void __launch_bounds__(256, 1)
k_mm_mma(const float* __restrict__ A, const float* __restrict__ bias,
         float* __restrict__ out, int nrows, int mode) {
    extern __shared__ float sm[];
    float* As = sm;                          // [128][AS_STRIDE]
    float* Bs = sm + 128 * AS_STRIDE;        // [128][BS_STRIDE]  (Bs[k][n])
    int tid = threadIdx.x;
    int row0 = blockIdx.x * 128;

    // ---- stage A tile and B (whole weight) into smem ----
#pragma unroll
    for (int i = 0; i < 16; i++) {
        int f = i * 256 + tid;               // 4096 float4 slots
        int r = f >> 5;
        int c = (f & 31) << 2;
        int gr = row0 + r;
        float4 v = make_float4(0.f, 0.f, 0.f, 0.f);
        if (gr < nrows) v = *(const float4*)&A[(size_t)gr * H + c];
        *(float4*)&As[r * AS_STRIDE + c] = v;
        float4 w = *(const float4*)&g_Bf[f * 4];
        *(float4*)&Bs[r * BS_STRIDE + c] = w;
    }
    __syncthreads();

    int wid = tid >> 5, lane = tid & 31;
    int wm = wid & 3, wn = wid >> 2;         // warp tile: rows wm*32, cols wn*64
    int g = lane >> 2, t = lane & 3;

    float acc[2][8][4];
#pragma unroll
    for (int mf = 0; mf < 2; mf++)
#pragma unroll
        for (int nf = 0; nf < 8; nf++)
#pragma unroll
            for (int k = 0; k < 4; k++) acc[mf][nf][k] = 0.f;

    for (int k0 = 0; k0 < H; k0 += 8) {
        uint32_t ah[2][4], al[2][4];
#pragma unroll
        for (int mf = 0; mf < 2; mf++) {
            int r = wm * 32 + mf * 16 + g;
            float x0 = As[r * AS_STRIDE + k0 + t];
            float x1 = As[(r + 8) * AS_STRIDE + k0 + t];
            float x2 = As[r * AS_STRIDE + k0 + t + 4];
            float x3 = As[(r + 8) * AS_STRIDE + k0 + t + 4];
            float h0 = to_tf32(x0), h1 = to_tf32(x1), h2 = to_tf32(x2), h3 = to_tf32(x3);
            ah[mf][0] = __float_as_uint(h0); al[mf][0] = __float_as_uint(to_tf32(x0 - h0));
            ah[mf][1] = __float_as_uint(h1); al[mf][1] = __float_as_uint(to_tf32(x1 - h1));
            ah[mf][2] = __float_as_uint(h2); al[mf][2] = __float_as_uint(to_tf32(x2 - h2));
            ah[mf][3] = __float_as_uint(h3); al[mf][3] = __float_as_uint(to_tf32(x3 - h3));
        }
        uint32_t bh[8][2], bl[8][2];
#pragma unroll
        for (int nf = 0; nf < 8; nf++) {
            int col = wn * 64 + nf * 8 + g;
            float y0 = Bs[(k0 + t) * BS_STRIDE + col];
            float y1 = Bs[(k0 + t + 4) * BS_STRIDE + col];
            float h0 = to_tf32(y0), h1 = to_tf32(y1);
            bh[nf][0] = __float_as_uint(h0); bl[nf][0] = __float_as_uint(to_tf32(y0 - h0));
            bh[nf][1] = __float_as_uint(h1); bl[nf][1] = __float_as_uint(to_tf32(y1 - h1));
        }
#pragma unroll
        for (int mf = 0; mf < 2; mf++)
#pragma unroll
            for (int nf = 0; nf < 8; nf++) {
                mma8(acc[mf][nf], ah[mf][0], ah[mf][1], ah[mf][2], ah[mf][3],
                     bh[nf][0], bh[nf][1]);
                mma8(acc[mf][nf], al[mf][0], al[mf][1], al[mf][2], al[mf][3],
                     bh[nf][0], bh[nf][1]);
                mma8(acc[mf][nf], ah[mf][0], ah[mf][1], ah[mf][2], ah[mf][3],
                     bl[nf][0], bl[nf][1]);
            }
    }

    // ---- epilogue ----
#pragma unroll
    for (int mf = 0; mf < 2; mf++) {
        int r0 = row0 + wm * 32 + mf * 16 + g;
        int r1 = r0 + 8;
#pragma unroll
        for (int nf = 0; nf < 8; nf++) {
            int col = wn * 64 + nf * 8 + t * 2;
            float* a = acc[mf][nf];
            if (mode == 0) {
                float c0 = g_cvec[col], c1 = g_cvec[col + 1];
                if (r0 < nrows) {
                    float d = g_dinv[r0];
                    float2 o = make_float2((a[0] + c0) * d, (a[1] + c1) * d);
                    *(float2*)&out[(size_t)r0 * H + col] = o;
                }
                if (r1 < nrows) {
                    float d = g_dinv[r1];
                    float2 o = make_float2((a[2] + c0) * d, (a[3] + c1) * d);
                    *(float2*)&out[(size_t)r1 * H + col] = o;
                }
            } else {
                float b0 = bias[col], b1 = bias[col + 1];
                if (r0 < nrows) {
                    float2 o = make_float2(fmaxf(a[0] + b0, 0.f), fmaxf(a[1] + b1, 0.f));
                    *(float2*)&out[(size_t)r0 * H + col] = o;
                }
                if (r1 < nrows) {
                    float2 o = make_float2(fmaxf(a[2] + b0, 0.f), fmaxf(a[3] + b1, 0.f));
                    *(float2*)&out[(size_t)r1 * H + col] = o;
                }
            }
        }
    }
}

// ---------------- CSR gather aggregation + relu epilogue ----------------
__global__ void k_gather(const float* __restrict__ p, float* __restrict__ out, int N) {
    int w = (blockIdx.x * blockDim.x + threadIdx.x) >> 5;
    int lane = threadIdx.x & 31;
    if (w >= N) return;
    float4 acc = *(const float4*)&p[(size_t)w * H + lane * 4];
    int beg = g_rowptr[w], end = g_rowptr[w + 1];
    int e = beg;
    for (; e + 1 < end; e += 2) {
        int s0 = g_srcs[e], s1 = g_srcs[e + 1];
        float4 v0 = *(const float4*)&p[(size_t)s0 * H + lane * 4];
        float4 v1 = *(const float4*)&p[(size_t)s1 * H + lane * 4];
        acc.x += v0.x; acc.y += v0.y; acc.z += v0.z; acc.w += v0.w;
        acc.x += v1.x; acc.y += v1.y; acc.z += v1.z; acc.w += v1.w;
    }
    if (e < end) {
        int s = g_srcs[e];
        float4 v = *(const float4*)&p[(size_t)s * H + lane * 4];
        acc.x += v.x; acc.y += v.y; acc.z += v.z; acc.w += v.w;
    }
    float d = g_dinv[w];
    float4 bb = *(const float4*)&g_bf[lane * 4];
    float4 o;
    o.x = fmaxf(fmaf(acc.x, d, bb.x), 0.f);
    o.y = fmaxf(fmaf(acc.y, d, bb.y), 0.f);
    o.z = fmaxf(fmaf(acc.z, d, bb.z), 0.f);
    o.w = fmaxf(fmaf(acc.w, d, bb.w), 0.f);
    *(float4*)&out[(size_t)w * H + lane * 4] = o;
}

// ---------------- gate scalar + weighted pooling ----------------
__global__ void k_gatepool(const float* __restrict__ r, const float* __restrict__ h,
                           const float* __restrict__ w2, const float* __restrict__ b2,
                           const void* batch, int N) {
    int w = (blockIdx.x * blockDim.x + threadIdx.x) >> 5;
    int lane = threadIdx.x & 31;
    if (w >= N) return;
    float4 rv = *(const float4*)&r[(size_t)w * H + lane * 4];
    float4 wv = *(const float4*)&w2[lane * 4];
    float d = rv.x * wv.x + rv.y * wv.y + rv.z * wv.z + rv.w * wv.w;
#pragma unroll
    for (int o = 16; o; o >>= 1) d += __shfl_xor_sync(0xffffffffu, d, o);
    float gate = 1.f / (1.f + expf(-(d + b2[0])));
    int b = g_flags[1] ? (int)((const long long*)batch)[w] : ((const int*)batch)[w];
    float4 hv = *(const float4*)&h[(size_t)w * H + lane * 4];
    float* dst = &g_pool[b * H + lane * 4];
    atomicAdd(dst + 0, hv.x * gate);
    atomicAdd(dst + 1, hv.y * gate);
    atomicAdd(dst + 2, hv.z * gate);
    atomicAdd(dst + 3, hv.w * gate);
}

// ---------------- BN over pooled graphs, folded into fc ----------------
__global__ void k_foldfc(const float* __restrict__ fcW, const float* __restrict__ fcb,
                         const float* __restrict__ gg, const float* __restrict__ gb) {
    int j = threadIdx.x;
    float s = 0.f, q = 0.f;
    for (int r = 0; r < NGR; r++) {
        float v = g_pool[r * H + j];
        s += v; q += v * v;
    }
    float mean = s / (float)NGR;
    float var = q / (float)NGR - mean * mean;
    float sj = rsqrtf(var + 1e-5f) * gg[j];
    float tj = gb[j] - mean * sj;
    __shared__ float tsh[H];
    tsh[j] = tj;
    for (int k = 0; k < H; k++) g_Wf[j * H + k] = sj * fcW[j * H + k];
    __syncthreads();
    float bb = fcb[j];
    for (int jj = 0; jj < H; jj++) bb += tsh[jj] * fcW[jj * H + j];
    g_bf[j] = bb;
}

// ---------------- fc + classifier + log_softmax ----------------
__global__ void k_final(const float* __restrict__ clsW, const float* __restrict__ clsb,
                        float* __restrict__ out) {
    __shared__ float gs[H], ys[H], ls[NCLS];
    int g = blockIdx.x, t = threadIdx.x;
    gs[t] = g_pool[g * H + t];
    __syncthreads();
    float a = g_bf[t];
#pragma unroll 8
    for (int j = 0; j < H; j++) a += gs[j] * g_Wf[j * H + t];
    ys[t] = fmaxf(a, 0.f);
    __syncthreads();
    if (t < NCLS) {
        float l = clsb[t];
        for (int k = 0; k < H; k++) l += ys[k] * clsW[k * NCLS + t];
        ls[t] = l;
    }
    __syncthreads();
    if (t == 0) {
        float m = ls[0];
        for (int c = 1; c < NCLS; c++) m = fmaxf(m, ls[c]);
        float se = 0.f;
        for (int c = 0; c < NCLS; c++) se += expf(ls[c] - m);
        float lse = m + logf(se);
        for (int c = 0; c < NCLS; c++) out[g * NCLS + c] = ls[c] - lse;
    }
}

// ---------------- host orchestration ----------------
extern "C" void kernel_launch(void* const* d_in, const int* in_sizes, int n_in,
                              void* d_out, int out_size) {
    const float* x           = (const float*)d_in[0];
    const void*  ei          = d_in[1];
    const void*  batch       = d_in[2];
    const float* bn_feat_g   = (const float*)d_in[3];
    const float* bn_feat_b   = (const float*)d_in[4];
    const float* conv_feat_W = (const float*)d_in[5];
    const float* conv_feat_b = (const float*)d_in[6];
    const float* conv_W      = (const float*)d_in[7];
    const float* conv_b      = (const float*)d_in[8];
    const float* bn_conv_g   = (const float*)d_in[9];
    const float* bn_conv_b   = (const float*)d_in[10];
    const float* gate_W1     = (const float*)d_in[11];
    const float* gate_b1     = (const float*)d_in[12];
    const float* gate_W2     = (const float*)d_in[13];
    const float* gate_b2     = (const float*)d_in[14];
    const float* fc_W        = (const float*)d_in[15];
    const float* fc_b        = (const float*)d_in[16];
    const float* bn_fc_g     = (const float*)d_in[17];
    const float* bn_fc_b     = (const float*)d_in[18];
    const float* cls_W       = (const float*)d_in[19];
    const float* cls_b       = (const float*)d_in[20];

    int N = in_sizes[0] / H;
    int E = in_sizes[1] / 2;

    float *bufA = nullptr, *bufB = nullptr;
    cudaGetSymbolAddress((void**)&bufA, g_bufA);
    cudaGetSymbolAddress((void**)&bufB, g_bufB);

    cudaFuncSetAttribute(k_mm_mma, cudaFuncAttributeMaxDynamicSharedMemorySize, SMEM_MM);

    int nb = (N + SCAN_BLK - 1) / SCAN_BLK;
    int mmg = (N + 127) / 128;

    k_detect<<<1, 32>>>(ei, batch, E, N);
    k_zero<<<256, 256>>>(N);
    k_hist<<<(E + 255) / 256, 256>>>(ei, E);
    k_dinv<<<(N + 255) / 256, 256>>>(N);
    k_scan1<<<nb, SCAN_BLK>>>(N);
    k_scan2<<<1, 32>>>(nb);
    k_scan3<<<(N + 255) / 256, 256>>>(N, E);
    k_fill<<<(E + 255) / 256, 256>>>(ei, E);

    // layer 0: BN(x) folded into conv_feat
    k_stats<<<NB_STATS, H>>>(x, N);
    k_fold<<<1, H>>>(conv_feat_W, conv_feat_b, bn_feat_g, bn_feat_b, N);
    k_mm_mma<<<mmg, 256, SMEM_MM>>>(x, nullptr, bufA, N, 0);
    k_gather<<<(N + 7) / 8, 256>>>(bufA, bufB, N);

    // layers 1..3
    for (int l = 0; l < 3; l++) {
        k_stats<<<NB_STATS, H>>>(bufB, N);
        k_fold<<<1, H>>>(conv_W + (size_t)l * H * H, conv_b + l * H,
                         bn_conv_g + l * H, bn_conv_b + l * H, N);
        k_mm_mma<<<mmg, 256, SMEM_MM>>>(bufB, nullptr, bufA, N, 0);
        k_gather<<<(N + 7) / 8, 256>>>(bufA, bufB, N);
    }

    // gate MLP + pooling
    k_prepgate<<<1, H>>>(gate_W1);
    k_mm_mma<<<mmg, 256, SMEM_MM>>>(bufB, gate_b1, bufA, N, 1);
    k_gatepool<<<((size_t)N * 32 + 255) / 256, 256>>>(bufA, bufB, gate_W2, gate_b2, batch, N);

    // fc + classifier + log_softmax
    k_foldfc<<<1, H>>>(fc_W, fc_b, bn_fc_g, bn_fc_b);
    k_final<<<NGR, H>>>(cls_W, cls_b, (float*)d_out);
}

// round 6
// speedup vs baseline: 1.1506x; 1.0477x over previous
#include <cuda_runtime.h>
#include <math.h>
#include <stdint.h>

#define H 128
#define NGR 256
#define NCLS 10
#define NMAX 50048
#define EMAX 600064
#define NB_STATS 256
#define SCAN_BLK 512
#define MAX_SB ((NMAX + SCAN_BLK - 1) / SCAN_BLK)

#define AS_STRIDE 132   // bank-conflict-free for A fragment pattern (4g+t)
#define BS_STRIDE 136   // bank-conflict-free for B fragment pattern (8t+g)
#define SMEM_MM ((128 * AS_STRIDE + 2 * 128 * BS_STRIDE) * 4)

// ---------------- device scratch (static; no allocation allowed) ----------------
__device__ float g_bufA[(size_t)NMAX * H];   // ping: GEMM output p (pre-dinv)
__device__ float g_bufB[(size_t)NMAX * H];   // pong: layer activations h
__device__ float g_dinv[NMAX];
__device__ int   g_deg[NMAX];
__device__ int   g_rowptr[NMAX + 1];
__device__ int   g_cursor[NMAX];
__device__ int   g_srcs[EMAX];
__device__ int   g_bsum[MAX_SB + 1];
__device__ float g_psum[NB_STATS * H];
__device__ float g_psq[NB_STATS * H];
__device__ float g_Wf[H * H];                // folded fc weight (k_foldfc/k_final)
__device__ float g_Bf_hi[H * H];             // BN-folded conv weight, tf32 hi part
__device__ float g_Bf_lo[H * H];             // tf32 lo part
__device__ float g_cvec[H];                  // pre-aggregation bias  c = t @ W
__device__ float g_bf[H];                    // post-aggregation bias
__device__ float g_pool[NGR * H];
__device__ int   g_flags[2];                 // [0]=edge idx is int64, [1]=batch is int64

// ---------------- helpers ----------------
__device__ __forceinline__ float to_tf32(float x) {
    float y;
    asm("cvt.rna.tf32.f32 %0, %1;" : "=f"(y) : "f"(x));
    return y;
}
__device__ __forceinline__ void mma8(float* acc, uint32_t a0, uint32_t a1, uint32_t a2,
                                     uint32_t a3, uint32_t b0, uint32_t b1) {
    asm volatile(
        "mma.sync.aligned.m16n8k8.row.col.f32.tf32.tf32.f32 "
        "{%0,%1,%2,%3},{%4,%5,%6,%7},{%8,%9},{%0,%1,%2,%3};"
        : "+f"(acc[0]), "+f"(acc[1]), "+f"(acc[2]), "+f"(acc[3])
        : "r"(a0), "r"(a1), "r"(a2), "r"(a3), "r"(b0), "r"(b1));
}

// ---------------- dtype-flexible index load ----------------
__device__ __forceinline__ int edge_idx(const void* p, long long i) {
    return g_flags[0] ? (int)((const long long*)p)[i] : ((const int*)p)[i];
}

__global__ void k_detect(const void* ei, const void* bt, int E, int N) {
    if (threadIdx.x == 0 && blockIdx.x == 0) {
        const unsigned long long* e64 = (const unsigned long long*)ei;
        int f = 1;
        for (int j = 0; j < 32; j++)
            if (e64[j] >= (1ULL << 31)) { f = 0; break; }
        g_flags[0] = f;
        const unsigned long long* b64 = (const unsigned long long*)bt;
        int f2 = 1;
        int half = N / 2;
        for (int j = half - 32; j < half; j++)
            if (b64[j] >= (1ULL << 31)) { f2 = 0; break; }
        g_flags[1] = f2;
    }
}

__global__ void k_zero(int N) {
    int tot = (N > NGR * H) ? N : (NGR * H);
    for (int i = blockIdx.x * blockDim.x + threadIdx.x; i < tot; i += gridDim.x * blockDim.x) {
        if (i < N) g_deg[i] = 0;
        if (i < NGR * H) g_pool[i] = 0.f;
    }
}

__global__ void k_hist(const void* ei, int E) {
    int e = blockIdx.x * blockDim.x + threadIdx.x;
    if (e < E) atomicAdd(&g_deg[edge_idx(ei, (long long)E + e)], 1);
}

// ---------------- CSR build (scan1 also emits dinv) ----------------
__global__ void k_scan1(int N) {
    __shared__ int sh[SCAN_BLK];
    int t = threadIdx.x;
    int i = blockIdx.x * SCAN_BLK + t;
    int v = (i < N) ? g_deg[i] : 0;
    if (i < N) g_dinv[i] = rsqrtf((float)v + 1.0f);
    sh[t] = v;
    __syncthreads();
    for (int off = 1; off < SCAN_BLK; off <<= 1) {
        int add = (t >= off) ? sh[t - off] : 0;
        __syncthreads();
        sh[t] += add;
        __syncthreads();
    }
    if (i < N) g_rowptr[i] = sh[t] - v;
    if (t == SCAN_BLK - 1) g_bsum[blockIdx.x] = sh[t];
}

__global__ void k_scan2(int nb) {
    if (threadIdx.x == 0 && blockIdx.x == 0) {
        int acc = 0;
        for (int b = 0; b < nb; b++) { int v = g_bsum[b]; g_bsum[b] = acc; acc += v; }
    }
}

__global__ void k_scan3(int N, int E) {
    int i = blockIdx.x * blockDim.x + threadIdx.x;
    if (i < N) {
        int r = g_rowptr[i] + g_bsum[i / SCAN_BLK];
        g_rowptr[i] = r;
        g_cursor[i] = r;
    }
    if (i == 0) g_rowptr[N] = E;
}

__global__ void k_fill(const void* ei, int E) {
    int e = blockIdx.x * blockDim.x + threadIdx.x;
    if (e < E) {
        int s = edge_idx(ei, e);
        int d = edge_idx(ei, (long long)E + e);
        g_srcs[atomicAdd(&g_cursor[d], 1)] = s;
    }
}

// ---------------- BN statistics ----------------
__global__ void k_stats(const float* __restrict__ h, int N) {
    int j = threadIdx.x;
    int b = blockIdx.x;
    float s = 0.f, q = 0.f;
    for (int r = b; r < N; r += NB_STATS) {
        float v = h[(size_t)r * H + j];
        s += v; q += v * v;
    }
    g_psum[b * H + j] = s;
    g_psq[b * H + j]  = q;
}

// Fold BN (y = x*s + t) into the following conv. Emits:
//   g_Bf_hi/lo[k][n] = tf32 split of s_k * W[k][n]   (coalesced row loop)
//   g_cvec[n] = sum_k t_k W[k][n]   (pre-aggregation constant)
//   g_bf[n]   = conv bias            (post-aggregation)
__global__ void k_fold(const float* __restrict__ W, const float* __restrict__ bias_in,
                       const float* __restrict__ gamma, const float* __restrict__ beta,
                       int Nrows) {
    int j = threadIdx.x;
    float s = 0.f, q = 0.f;
    for (int b = 0; b < NB_STATS; b++) { s += g_psum[b * H + j]; q += g_psq[b * H + j]; }
    float mean = s / (float)Nrows;
    float var  = q / (float)Nrows - mean * mean;
    float sj = rsqrtf(var + 1e-5f) * gamma[j];
    float tj = beta[j] - mean * sj;
    __shared__ float ssh[H], tsh[H];
    ssh[j] = sj;
    tsh[j] = tj;
    __syncthreads();
    float cc = 0.f;
#pragma unroll 4
    for (int r = 0; r < H; r++) {
        float wrj = W[r * H + j];          // coalesced across threads
        float w = ssh[r] * wrj;
        float hi = to_tf32(w);
        g_Bf_hi[r * H + j] = hi;
        g_Bf_lo[r * H + j] = to_tf32(w - hi);
        cc += tsh[r] * wrj;
    }
    g_cvec[j] = cc;
    g_bf[j] = bias_in[j];
}

__global__ void k_prepgate(const float* __restrict__ W) {
    int j = threadIdx.x;
#pragma unroll 4
    for (int r = 0; r < H; r++) {
        float w = W[r * H + j];
        float hi = to_tf32(w);
        g_Bf_hi[r * H + j] = hi;
        g_Bf_lo[r * H + j] = to_tf32(w - hi);
    }
}

// ---------------- tensor-core GEMM via mma.sync tf32, 3xTF32 split ----------------
// out[128tile, 128] = A @ Bf, fused epilogue.
// mode 0: out = acc + cvec[col]            (dinv applied later in gather)
// mode 1: out = relu(acc + bias[col])
__global__ void __launch_bounds__(256, 1)
k_mm_mma(const float* __restrict__ A, const float* __restrict__ bias,
         float* __restrict__ out, int nrows, int mode) {
    extern __shared__ float sm[];
    float* As    = sm;                                   // [128][AS_STRIDE]
    float* Bs_hi = sm + 128 * AS_STRIDE;                 // [128][BS_STRIDE]
    float* Bs_lo = sm + 128 * AS_STRIDE + 128 * BS_STRIDE;
    int tid = threadIdx.x;
    int row0 = blockIdx.x * 128;

    // ---- stage A tile (raw) and B (pre-split hi/lo) into smem ----
#pragma unroll
    for (int i = 0; i < 16; i++) {
        int f = i * 256 + tid;               // 4096 float4 slots
        int r = f >> 5;
        int c = (f & 31) << 2;
        int gr = row0 + r;
        float4 v = make_float4(0.f, 0.f, 0.f, 0.f);
        if (gr < nrows) v = *(const float4*)&A[(size_t)gr * H + c];
        *(float4*)&As[r * AS_STRIDE + c] = v;
        float4 wh = *(const float4*)&g_Bf_hi[f * 4];
        float4 wl = *(const float4*)&g_Bf_lo[f * 4];
        *(float4*)&Bs_hi[r * BS_STRIDE + c] = wh;
        *(float4*)&Bs_lo[r * BS_STRIDE + c] = wl;
    }
    __syncthreads();

    int wid = tid >> 5, lane = tid & 31;
    int wm = wid & 3, wn = wid >> 2;         // warp tile: rows wm*32, cols wn*64
    int g = lane >> 2, t = lane & 3;

    float acc[2][8][4];
#pragma unroll
    for (int mf = 0; mf < 2; mf++)
#pragma unroll
        for (int nf = 0; nf < 8; nf++)
#pragma unroll
            for (int k = 0; k < 4; k++) acc[mf][nf][k] = 0.f;

    for (int k0 = 0; k0 < H; k0 += 8) {
        uint32_t ah[2][4], al[2][4];
#pragma unroll
        for (int mf = 0; mf < 2; mf++) {
            int r = wm * 32 + mf * 16 + g;
            float x0 = As[r * AS_STRIDE + k0 + t];
            float x1 = As[(r + 8) * AS_STRIDE + k0 + t];
            float x2 = As[r * AS_STRIDE + k0 + t + 4];
            float x3 = As[(r + 8) * AS_STRIDE + k0 + t + 4];
            float h0 = to_tf32(x0), h1 = to_tf32(x1), h2 = to_tf32(x2), h3 = to_tf32(x3);
            ah[mf][0] = __float_as_uint(h0); al[mf][0] = __float_as_uint(to_tf32(x0 - h0));
            ah[mf][1] = __float_as_uint(h1); al[mf][1] = __float_as_uint(to_tf32(x1 - h1));
            ah[mf][2] = __float_as_uint(h2); al[mf][2] = __float_as_uint(to_tf32(x2 - h2));
            ah[mf][3] = __float_as_uint(h3); al[mf][3] = __float_as_uint(to_tf32(x3 - h3));
        }
        uint32_t bh[8][2], bl[8][2];
#pragma unroll
        for (int nf = 0; nf < 8; nf++) {
            int col = wn * 64 + nf * 8 + g;
            bh[nf][0] = __float_as_uint(Bs_hi[(k0 + t) * BS_STRIDE + col]);
            bh[nf][1] = __float_as_uint(Bs_hi[(k0 + t + 4) * BS_STRIDE + col]);
            bl[nf][0] = __float_as_uint(Bs_lo[(k0 + t) * BS_STRIDE + col]);
            bl[nf][1] = __float_as_uint(Bs_lo[(k0 + t + 4) * BS_STRIDE + col]);
        }
#pragma unroll
        for (int mf = 0; mf < 2; mf++)
#pragma unroll
            for (int nf = 0; nf < 8; nf++) {
                mma8(acc[mf][nf], ah[mf][0], ah[mf][1], ah[mf][2], ah[mf][3],
                     bh[nf][0], bh[nf][1]);
                mma8(acc[mf][nf], al[mf][0], al[mf][1], al[mf][2], al[mf][3],
                     bh[nf][0], bh[nf][1]);
                mma8(acc[mf][nf], ah[mf][0], ah[mf][1], ah[mf][2], ah[mf][3],
                     bl[nf][0], bl[nf][1]);
            }
    }

    // ---- epilogue ----
#pragma unroll
    for (int mf = 0; mf < 2; mf++) {
        int r0 = row0 + wm * 32 + mf * 16 + g;
        int r1 = r0 + 8;
#pragma unroll
        for (int nf = 0; nf < 8; nf++) {
            int col = wn * 64 + nf * 8 + t * 2;
            float* a = acc[mf][nf];
            if (mode == 0) {
                float c0 = g_cvec[col], c1 = g_cvec[col + 1];
                if (r0 < nrows)
                    *(float2*)&out[(size_t)r0 * H + col] = make_float2(a[0] + c0, a[1] + c1);
                if (r1 < nrows)
                    *(float2*)&out[(size_t)r1 * H + col] = make_float2(a[2] + c0, a[3] + c1);
            } else {
                float b0 = bias[col], b1 = bias[col + 1];
                if (r0 < nrows)
                    *(float2*)&out[(size_t)r0 * H + col] =
                        make_float2(fmaxf(a[0] + b0, 0.f), fmaxf(a[1] + b1, 0.f));
                if (r1 < nrows)
                    *(float2*)&out[(size_t)r1 * H + col] =
                        make_float2(fmaxf(a[2] + b0, 0.f), fmaxf(a[3] + b1, 0.f));
            }
        }
    }
}

// ---------------- CSR gather aggregation + relu epilogue ----------------
// out[i] = relu( dinv_i * (dinv_i*p_i + sum_e dinv_s*p_s) + conv_bias )
__global__ void k_gather(const float* __restrict__ p, float* __restrict__ out, int N) {
    int w = (blockIdx.x * blockDim.x + threadIdx.x) >> 5;
    int lane = threadIdx.x & 31;
    if (w >= N) return;
    float dw = g_dinv[w];
    float4 self = *(const float4*)&p[(size_t)w * H + lane * 4];
    float4 acc = make_float4(self.x * dw, self.y * dw, self.z * dw, self.w * dw);
    int beg = g_rowptr[w], end = g_rowptr[w + 1];
    int e = beg;
    for (; e + 3 < end; e += 4) {
        int s0 = g_srcs[e], s1 = g_srcs[e + 1], s2 = g_srcs[e + 2], s3 = g_srcs[e + 3];
        float d0 = g_dinv[s0], d1 = g_dinv[s1], d2 = g_dinv[s2], d3 = g_dinv[s3];
        float4 v0 = *(const float4*)&p[(size_t)s0 * H + lane * 4];
        float4 v1 = *(const float4*)&p[(size_t)s1 * H + lane * 4];
        float4 v2 = *(const float4*)&p[(size_t)s2 * H + lane * 4];
        float4 v3 = *(const float4*)&p[(size_t)s3 * H + lane * 4];
        acc.x = fmaf(v0.x, d0, acc.x); acc.y = fmaf(v0.y, d0, acc.y);
        acc.z = fmaf(v0.z, d0, acc.z); acc.w = fmaf(v0.w, d0, acc.w);
        acc.x = fmaf(v1.x, d1, acc.x); acc.y = fmaf(v1.y, d1, acc.y);
        acc.z = fmaf(v1.z, d1, acc.z); acc.w = fmaf(v1.w, d1, acc.w);
        acc.x = fmaf(v2.x, d2, acc.x); acc.y = fmaf(v2.y, d2, acc.y);
        acc.z = fmaf(v2.z, d2, acc.z); acc.w = fmaf(v2.w, d2, acc.w);
        acc.x = fmaf(v3.x, d3, acc.x); acc.y = fmaf(v3.y, d3, acc.y);
        acc.z = fmaf(v3.z, d3, acc.z); acc.w = fmaf(v3.w, d3, acc.w);
    }
    for (; e < end; e++) {
        int s = g_srcs[e];
        float ds = g_dinv[s];
        float4 v = *(const float4*)&p[(size_t)s * H + lane * 4];
        acc.x = fmaf(v.x, ds, acc.x); acc.y = fmaf(v.y, ds, acc.y);
        acc.z = fmaf(v.z, ds, acc.z); acc.w = fmaf(v.w, ds, acc.w);
    }
    float4 bb = *(const float4*)&g_bf[lane * 4];
    float4 o;
    o.x = fmaxf(fmaf(acc.x, dw, bb.x), 0.f);
    o.y = fmaxf(fmaf(acc.y, dw, bb.y), 0.f);
    o.z = fmaxf(fmaf(acc.z, dw, bb.z), 0.f);
    o.w = fmaxf(fmaf(acc.w, dw, bb.w), 0.f);
    *(float4*)&out[(size_t)w * H + lane * 4] = o;
}

// ---------------- gate scalar + weighted pooling ----------------
__global__ void k_gatepool(const float* __restrict__ r, const float* __restrict__ h,
                           const float* __restrict__ w2, const float* __restrict__ b2,
                           const void* batch, int N) {
    int w = (blockIdx.x * blockDim.x + threadIdx.x) >> 5;
    int lane = threadIdx.x & 31;
    if (w >= N) return;
    float4 rv = *(const float4*)&r[(size_t)w * H + lane * 4];
    float4 wv = *(const float4*)&w2[lane * 4];
    float d = rv.x * wv.x + rv.y * wv.y + rv.z * wv.z + rv.w * wv.w;
#pragma unroll
    for (int o = 16; o; o >>= 1) d += __shfl_xor_sync(0xffffffffu, d, o);
    float gate = 1.f / (1.f + expf(-(d + b2[0])));
    int b = g_flags[1] ? (int)((const long long*)batch)[w] : ((const int*)batch)[w];
    float4 hv = *(const float4*)&h[(size_t)w * H + lane * 4];
    float* dst = &g_pool[b * H + lane * 4];
    atomicAdd(dst + 0, hv.x * gate);
    atomicAdd(dst + 1, hv.y * gate);
    atomicAdd(dst + 2, hv.z * gate);
    atomicAdd(dst + 3, hv.w * gate);
}

// ---------------- BN over pooled graphs, folded into fc ----------------
__global__ void k_foldfc(const float* __restrict__ fcW, const float* __restrict__ fcb,
                         const float* __restrict__ gg, const float* __restrict__ gb) {
    int j = threadIdx.x;
    float s = 0.f, q = 0.f;
    for (int r = 0; r < NGR; r++) {
        float v = g_pool[r * H + j];
        s += v; q += v * v;
    }
    float mean = s / (float)NGR;
    float var = q / (float)NGR - mean * mean;
    float sj = rsqrtf(var + 1e-5f) * gg[j];
    float tj = gb[j] - mean * sj;
    __shared__ float ssh[H], tsh[H];
    ssh[j] = sj;
    tsh[j] = tj;
    __syncthreads();
    float bb = fcb[j];
#pragma unroll 4
    for (int r = 0; r < H; r++) {
        float wrj = fcW[r * H + j];
        g_Wf[r * H + j] = ssh[r] * wrj;       // coalesced
        bb += tsh[r] * wrj;
    }
    g_bf[j] = bb;
}

// ---------------- fc + classifier + log_softmax ----------------
__global__ void k_final(const float* __restrict__ clsW, const float* __restrict__ clsb,
                        float* __restrict__ out) {
    __shared__ float gs[H], ys[H], ls[NCLS];
    int g = blockIdx.x, t = threadIdx.x;
    gs[t] = g_pool[g * H + t];
    __syncthreads();
    float a = g_bf[t];
#pragma unroll 8
    for (int j = 0; j < H; j++) a += gs[j] * g_Wf[j * H + t];
    ys[t] = fmaxf(a, 0.f);
    __syncthreads();
    if (t < NCLS) {
        float l = clsb[t];
        for (int k = 0; k < H; k++) l += ys[k] * clsW[k * NCLS + t];
        ls[t] = l;
    }
    __syncthreads();
    if (t == 0) {
        float m = ls[0];
        for (int c = 1; c < NCLS; c++) m = fmaxf(m, ls[c]);
        float se = 0.f;
        for (int c = 0; c < NCLS; c++) se += expf(ls[c] - m);
        float lse = m + logf(se);
        for (int c = 0; c < NCLS; c++) out[g * NCLS + c] = ls[c] - lse;
    }
}

// ---------------- host orchestration ----------------
extern "C" void kernel_launch(void* const* d_in, const int* in_sizes, int n_in,
                              void* d_out, int out_size) {
    const float* x           = (const float*)d_in[0];
    const void*  ei          = d_in[1];
    const void*  batch       = d_in[2];
    const float* bn_feat_g   = (const float*)d_in[3];
    const float* bn_feat_b   = (const float*)d_in[4];
    const float* conv_feat_W = (const float*)d_in[5];
    const float* conv_feat_b = (const float*)d_in[6];
    const float* conv_W      = (const float*)d_in[7];
    const float* conv_b      = (const float*)d_in[8];
    const float* bn_conv_g   = (const float*)d_in[9];
    const float* bn_conv_b   = (const float*)d_in[10];
    const float* gate_W1     = (const float*)d_in[11];
    const float* gate_b1     = (const float*)d_in[12];
    const float* gate_W2     = (const float*)d_in[13];
    const float* gate_b2     = (const float*)d_in[14];
    const float* fc_W        = (const float*)d_in[15];
    const float* fc_b        = (const float*)d_in[16];
    const float* bn_fc_g     = (const float*)d_in[17];
    const float* bn_fc_b     = (const float*)d_in[18];
    const float* cls_W       = (const float*)d_in[19];
    const float* cls_b       = (const float*)d_in[20];

    int N = in_sizes[0] / H;
    int E = in_sizes[1] / 2;

    float *bufA = nullptr, *bufB = nullptr;
    cudaGetSymbolAddress((void**)&bufA, g_bufA);
    cudaGetSymbolAddress((void**)&bufB, g_bufB);

    cudaFuncSetAttribute(k_mm_mma, cudaFuncAttributeMaxDynamicSharedMemorySize, SMEM_MM);

    int nb = (N + SCAN_BLK - 1) / SCAN_BLK;
    int mmg = (N + 127) / 128;

    // layer-0 GEMM first (depends only on x + fold) so ncu's fixed capture slot
    // lands on k_mm_mma; CSR build follows and completes before the gather.
    k_detect<<<1, 32>>>(ei, batch, E, N);               // 1
    k_stats<<<NB_STATS, H>>>(x, N);                     // 2
    k_fold<<<1, H>>>(conv_feat_W, conv_feat_b, bn_feat_g, bn_feat_b, N);  // 3
    k_mm_mma<<<mmg, 256, SMEM_MM>>>(x, nullptr, bufA, N, 0);              // 4 <- profiled
    k_zero<<<256, 256>>>(N);                            // 5
    k_hist<<<(E + 255) / 256, 256>>>(ei, E);            // 6
    k_scan1<<<nb, SCAN_BLK>>>(N);                       // 7 (also dinv)
    k_scan2<<<1, 32>>>(nb);                             // 8
    k_scan3<<<(N + 255) / 256, 256>>>(N, E);            // 9
    k_fill<<<(E + 255) / 256, 256>>>(ei, E);            // 10
    k_gather<<<(N + 7) / 8, 256>>>(bufA, bufB, N);      // 11

    // layers 1..3
    for (int l = 0; l < 3; l++) {
        k_stats<<<NB_STATS, H>>>(bufB, N);
        k_fold<<<1, H>>>(conv_W + (size_t)l * H * H, conv_b + l * H,
                         bn_conv_g + l * H, bn_conv_b + l * H, N);
        k_mm_mma<<<mmg, 256, SMEM_MM>>>(bufB, nullptr, bufA, N, 0);
        k_gather<<<(N + 7) / 8, 256>>>(bufA, bufB, N);
    }

    // gate MLP + pooling
    k_prepgate<<<1, H>>>(gate_W1);
    k_mm_mma<<<mmg, 256, SMEM_MM>>>(bufB, gate_b1, bufA, N, 1);
    k_gatepool<<<((size_t)N * 32 + 255) / 256, 256>>>(bufA, bufB, gate_W2, gate_b2, batch, N);

    // fc + classifier + log_softmax
    k_foldfc<<<1, H>>>(fc_W, fc_b, bn_fc_g, bn_fc_b);
    k_final<<<NGR, H>>>(cls_W, cls_b, (float*)d_out);
}